// round 17
// baseline (speedup 1.0000x reference)
#include <cuda_runtime.h>
#include <cuda_bf16.h>

// StixelLoss v17: R16 engine + depth-2 software pipeline (MLP=4) at occ~75%.
// inputs:  (B=256, C=2, H=192, W=256) f32 in (1e-4, 1-1e-4)
// targets: (1, B, C, H, W) f32
// out:     scalar f32 = 1.0*bce_mean + 0.001*cuts + 0.1*dense

#define HH    192
#define WW    256
#define NBC   512
#define NBLK  (NBC * 2)       // 1024 blocks: (b, c, w-half)
#define WH    128             // columns per block
#define NQ    32              // float4 quads per block row
#define NSEG  8               // 24-row segments
#define SEGH  24
#define TABN  1216            // 1/d^3 lookup incl. sentinel fold
#define SENT  (-1000)         // prev sentinel: pos-SENT in [1001,1190] -> tab 0

__device__ float    g_acc = 0.0f;
__device__ unsigned g_cnt = 0u;

// Read-only load, 256B L2 promotion granule.
__device__ __forceinline__ float4 ldnc_256(const float4* p) {
    float4 v;
    asm volatile("ld.global.nc.L2::256B.v4.f32 {%0,%1,%2,%3}, [%4];"
                 : "=f"(v.x), "=f"(v.y), "=f"(v.z), "=f"(v.w)
                 : "l"(p));
    return v;
}

__global__ __launch_bounds__(256, 6)
void stixel_kernel(const float* __restrict__ inp,
                   const float* __restrict__ tgt,
                   float* __restrict__ out) {
    const int bc = blockIdx.x >> 1;          // b*2 + c
    const int wh = blockIdx.x & 1;           // w-half
    const int c  = bc & 1;
    const int q  = threadIdx.x & (NQ - 1);   // quad (cols 4q..4q+3 in half)
    const int s  = threadIdx.x >> 5;         // h-segment 0..7
    const int h0 = s * SEGH;

    __shared__ float        tab[TABN];
    __shared__ unsigned int smask[NSEG][WH];
    __shared__ float        sred[8];

    // channel-1 blocks: fill 1/d^3 table (zero outside [1,190])
    if (c == 1) {
        for (int k = threadIdx.x; k < TABN; k += 256) {
            float fd = (float)k;
            tab[k] = (k >= 1 && k < HH - 1) ? (1.0f / (fd * fd * fd)) : 0.0f;
        }
    }

    const size_t base = (size_t)bc * (HH * WW) + (size_t)h0 * WW
                      + (size_t)wh * WH + 4 * q;
    const float4* ip4 = (const float4*)(inp + base);
    const float4* tp4 = (const float4*)(tgt + base);

    float bce = 0.0f;
    unsigned int m0 = 0, m1 = 0, m2 = 0, m3 = 0;

    // depth-2 software pipeline: iteration i+1's loads issue before
    // iteration i's math -> 4 float4 loads in flight per thread.
    float4 pc = ldnc_256(ip4);
    float4 tc = ldnc_256(tp4);

    #pragma unroll
    for (int i = 0; i < SEGH; ++i) {
        float4 pn, tn;
        if (i < SEGH - 1) {
            pn = ldnc_256(ip4 + (i + 1) * (WW / 4));
            tn = ldnc_256(tp4 + (i + 1) * (WW / 4));
        }
        {
            float lp = __log2f(pc.x), l1p = __log2f(1.0f - pc.x);
            bce += l1p + tc.x * (lp - l1p);
            if (pc.x > 0.5f) m0 |= (1u << i);
        }
        {
            float lp = __log2f(pc.y), l1p = __log2f(1.0f - pc.y);
            bce += l1p + tc.y * (lp - l1p);
            if (pc.y > 0.5f) m1 |= (1u << i);
        }
        {
            float lp = __log2f(pc.z), l1p = __log2f(1.0f - pc.z);
            bce += l1p + tc.z * (lp - l1p);
            if (pc.z > 0.5f) m2 |= (1u << i);
        }
        {
            float lp = __log2f(pc.w), l1p = __log2f(1.0f - pc.w);
            bce += l1p + tc.w * (lp - l1p);
            if (pc.w > 0.5f) m3 |= (1u << i);
        }
        pc = pn; tc = tn;
    }

    float dense = 0.0f;
    int   cuts  = 0;

    if (c == 0) {
        cuts = __popc(m0) + __popc(m1) + __popc(m2) + __popc(m3);
    } else {
        smask[s][4 * q + 0] = m0;
        smask[s][4 * q + 1] = m1;
        smask[s][4 * q + 2] = m2;
        smask[s][4 * q + 3] = m3;
        __syncthreads();

        const int col  = threadIdx.x & (WH - 1);
        const int half = threadIdx.x >> 7;   // 0: rows 0..95, 1: rows 96..191

        int prev = SENT;
        if (half == 1) {
            // initial prev = last hit in rows 0..95 (bit 0 of seg0 invisible)
            unsigned int u3 = smask[3][col];
            unsigned int u2 = smask[2][col];
            unsigned int u1 = smask[1][col];
            unsigned int u0 = smask[0][col] & ~1u;
            if      (u3) prev = 72 + 31 - __clz(u3);
            else if (u2) prev = 48 + 31 - __clz(u2);
            else if (u1) prev = 24 + 31 - __clz(u1);
            else if (u0) prev =      31 - __clz(u0);
        }

        #pragma unroll
        for (int k = 0; k < 4; ++k) {
            unsigned int w = smask[half * 4 + k][col];
            if (half == 0 && k == 0) w &= ~1u;          // h=0 hit invisible
            if (half == 1 && k == 3) w &= ~(1u << 23);  // h=191 excluded
            const int rowbase = (half * 4 + k) * SEGH;
            while (w) {
                int b = __ffs(w) - 1;
                w &= (w - 1);
                int pos = rowbase + b;
                dense += tab[pos - prev];   // tab==0 when prev is sentinel
                prev = pos;
            }
        }
    }

    // combine (ALPHA=1, BETA=0.001, GAMMA=0.1); bce is in log2 units
    const float SCALE_BCE = -0.69314718055994531f /
                            (float)((size_t)NBC * HH * WW);
    float val = bce * SCALE_BCE + 0.001f * (float)cuts + 0.1f * dense;

    // block reduction over 256 threads
    #pragma unroll
    for (int off = 16; off > 0; off >>= 1)
        val += __shfl_down_sync(0xffffffffu, val, off);
    const int lane = threadIdx.x & 31;
    const int wid  = threadIdx.x >> 5;
    if (lane == 0) sred[wid] = val;
    __syncthreads();

    if (wid == 0) {
        val = (lane < 8) ? sred[lane] : 0.0f;
        #pragma unroll
        for (int off = 4; off > 0; off >>= 1)
            val += __shfl_down_sync(0xffffffffu, val, off);
        if (lane == 0) {
            atomicAdd(&g_acc, val);
            __threadfence();
            unsigned old = atomicAdd(&g_cnt, 1u);
            if (old == NBLK - 1) {
                // last block: publish result, reset scratch for next replay
                float total = atomicAdd(&g_acc, 0.0f);  // coherent read
                out[0] = total;
                __threadfence();
                g_acc = 0.0f;
                g_cnt = 0u;
            }
        }
    }
}

extern "C" void kernel_launch(void* const* d_in, const int* in_sizes, int n_in,
                              void* d_out, int out_size) {
    const float* inp = (const float*)d_in[0];
    const float* tgt = (const float*)d_in[1];
    float* out = (float*)d_out;

    stixel_kernel<<<NBLK, 256>>>(inp, tgt, out);
}